// round 2
// baseline (speedup 1.0000x reference)
#include <cuda_runtime.h>
#include <cstddef>

#define NN   50000
#define DEG  16
#define FE   16
#define DH   128
#define DC   144     // DH + FE
#define NL   3
#define NG   64
#define DOUT 10
#define BM   64
#define SA1_STRIDE 148
#define SA2_STRIDE 132
#define BN_SCALE 0.9999950000374997f

#define GRID_M ((NN + BM - 1) / BM)   // 782
#define POOLN  ((NL + 1) * NG * DH)   // 32768

// ---- device scratch (no allocation allowed) ----
__device__ float g_h1[(size_t)NN * DH];
__device__ float g_hb0[(size_t)NN * DH];
__device__ float g_hb1[(size_t)NN * DH];
__device__ float g_edge_rep[(size_t)NN * FE];
__device__ float g_pool[POOLN];

// ---------------------------------------------------------------------------
__global__ void k_zero(float* __restrict__ p, int n) {
    int i = blockIdx.x * blockDim.x + threadIdx.x;
    if (i < n) p[i] = 0.f;
}

// edge_rep[i][f] = 1 + sum_{k<16} edge_attr[i*16+k][f]
__global__ void k_edge_rep(const float* __restrict__ ea, float* __restrict__ er) {
    int t = blockIdx.x * blockDim.x + threadIdx.x;
    if (t >= NN * FE) return;
    int i = t >> 4, f = t & 15;
    const float* base = ea + ((size_t)i * DEG) * FE + f;
    float s = 1.f;
#pragma unroll
    for (int k = 0; k < DEG; k++) s += __ldg(base + k * FE);
    er[t] = s;
}

// per-graph add pool of a dense (N,128) matrix; batch is sorted.
// block = 128 threads (one per column), tile = 256 rows.
__global__ void k_pool_rep(const float* __restrict__ h, const int* __restrict__ batch,
                           float* __restrict__ pool) {
    int c  = threadIdx.x;
    int m0 = blockIdx.x * 256;
    float s = 0.f;
    int curg = -1;
    for (int r = 0; r < 256; r++) {
        int node = m0 + r;
        if (node >= NN) break;
        int g = __ldg(&batch[node]);
        if (g != curg) {
            if (curg >= 0) atomicAdd(&pool[curg * DH + c], s);
            s = 0.f; curg = g;
        }
        s += __ldg(&h[(size_t)node * DH + c]);
    }
    if (curg >= 0) atomicAdd(&pool[curg * DH + c], s);
}

// ---------------------------------------------------------------------------
// Fused gather + GEMM1 + BN + ReLU.
// pooled[:, :128] = (1+eps)*h[i] + sum_k h[dst[i*16+k]];  pooled[:, 128:144] = edge_rep + eps
// h1 = relu(alpha * (pooled @ W1) + (alpha*b1 + be1)),  alpha = g1*BN_SCALE
__global__ void k_gg1(const float* __restrict__ hin,
                      const int*   __restrict__ edge_dst,
                      const float* __restrict__ eps, int l,
                      const float* __restrict__ W1,
                      const float* __restrict__ b1,
                      const float* __restrict__ g1,
                      const float* __restrict__ be1,
                      const float* __restrict__ er,
                      float* __restrict__ hout) {
    extern __shared__ float smem[];
    float* sW = smem;                 // [144][128]
    float* sA = smem + DC * DH;       // [64][148]
    int tid = threadIdx.x;
    int m0  = blockIdx.x * BM;
    const float* Wl = W1 + (size_t)l * DC * DH;
#pragma unroll
    for (int i = tid; i < DC * DH / 4; i += 256)
        ((float4*)sW)[i] = __ldg(((const float4*)Wl) + i);

    float epsv = __ldg(&eps[l]);

    // ---- build A tile (gather) ----
    int r = tid >> 2, q = tid & 3;     // 64 rows x 4 col-groups of 32 floats
    int node = m0 + r;
    float4 a[8];
    if (node < NN) {
        const float4* hr = (const float4*)(hin + (size_t)node * DH + q * 32);
        float e1 = 1.f + epsv;
#pragma unroll
        for (int j = 0; j < 8; j++) {
            float4 v = __ldg(hr + j);
            a[j].x = v.x * e1; a[j].y = v.y * e1; a[j].z = v.z * e1; a[j].w = v.w * e1;
        }
        const int* ed = edge_dst + (size_t)node * DEG;
#pragma unroll
        for (int k = 0; k < DEG; k++) {
            int d = __ldg(ed + k);
            const float4* nr = (const float4*)(hin + (size_t)d * DH + q * 32);
#pragma unroll
            for (int j = 0; j < 8; j++) {
                float4 v = __ldg(nr + j);
                a[j].x += v.x; a[j].y += v.y; a[j].z += v.z; a[j].w += v.w;
            }
        }
    } else {
#pragma unroll
        for (int j = 0; j < 8; j++) a[j] = make_float4(0.f, 0.f, 0.f, 0.f);
    }
    float4* arow = (float4*)(sA + r * SA1_STRIDE + q * 32);
#pragma unroll
    for (int j = 0; j < 8; j++) arow[j] = a[j];
    {   // edge-feature columns 128..143 (q picks one float4 of 4)
        float4 e;
        if (node < NN) {
            float4 v = __ldg(((const float4*)(er + (size_t)node * FE)) + q);
            e.x = v.x + epsv; e.y = v.y + epsv; e.z = v.z + epsv; e.w = v.w + epsv;
        } else e = make_float4(0.f, 0.f, 0.f, 0.f);
        *(((float4*)(sA + r * SA1_STRIDE + DH)) + q) = e;
    }
    __syncthreads();

    // ---- GEMM: 256 thr = 16x16, each 4 rows x 8 cols ----
    int ty = tid >> 4, tx = tid & 15;
    float acc[4][8];
#pragma unroll
    for (int i = 0; i < 4; i++)
#pragma unroll
        for (int j = 0; j < 8; j++) acc[i][j] = 0.f;
    const float* A0 = sA + (ty * 4) * SA1_STRIDE;
#pragma unroll 4
    for (int k = 0; k < DC; k++) {
        float areg[4];
#pragma unroll
        for (int i = 0; i < 4; i++) areg[i] = A0[i * SA1_STRIDE + k];
        float4 bv0 = *(const float4*)(sW + k * DH + tx * 8);
        float4 bv1 = *(const float4*)(sW + k * DH + tx * 8 + 4);
        float breg[8] = {bv0.x, bv0.y, bv0.z, bv0.w, bv1.x, bv1.y, bv1.z, bv1.w};
#pragma unroll
        for (int i = 0; i < 4; i++)
#pragma unroll
            for (int j = 0; j < 8; j++) acc[i][j] += areg[i] * breg[j];
    }

    // ---- epilogue: BN + ReLU ----
    float al[8], bt[8];
#pragma unroll
    for (int j = 0; j < 8; j++) {
        int c = tx * 8 + j;
        float aa = __ldg(&g1[l * DH + c]) * BN_SCALE;
        al[j] = aa;
        bt[j] = aa * __ldg(&b1[l * DH + c]) + __ldg(&be1[l * DH + c]);
    }
#pragma unroll
    for (int i = 0; i < 4; i++) {
        int nodei = m0 + ty * 4 + i;
        if (nodei < NN) {
            float v[8];
#pragma unroll
            for (int j = 0; j < 8; j++) v[j] = fmaxf(al[j] * acc[i][j] + bt[j], 0.f);
            float4* dst = (float4*)(hout + (size_t)nodei * DH + tx * 8);
            dst[0] = make_float4(v[0], v[1], v[2], v[3]);
            dst[1] = make_float4(v[4], v[5], v[6], v[7]);
        }
    }
}

// ---------------------------------------------------------------------------
// GEMM2 + BN + ReLU + per-graph pooling of this layer's output.
__global__ void k_gemm2(const float* __restrict__ h1, int l,
                        const float* __restrict__ W2,
                        const float* __restrict__ b2,
                        const float* __restrict__ bng,
                        const float* __restrict__ bnb,
                        const int*   __restrict__ batch,
                        float* __restrict__ hout,
                        float* __restrict__ pool) {
    extern __shared__ float smem[];
    float* sW = smem;                        // [128][128]
    float* sA = smem + DH * DH;              // [64][132] (A tile, then h tile)
    int*  sB  = (int*)(sA + BM * SA2_STRIDE);
    int tid = threadIdx.x;
    int m0  = blockIdx.x * BM;
    const float* Wl = W2 + (size_t)l * DH * DH;
#pragma unroll
    for (int i = tid; i < DH * DH / 4; i += 256)
        ((float4*)sW)[i] = __ldg(((const float4*)Wl) + i);

    int r = tid >> 2, q = tid & 3;
    int node = m0 + r;
    {
        float4* arow = (float4*)(sA + r * SA2_STRIDE + q * 32);
        if (node < NN) {
            const float4* hr = (const float4*)(h1 + (size_t)node * DH + q * 32);
#pragma unroll
            for (int j = 0; j < 8; j++) arow[j] = __ldg(hr + j);
        } else {
#pragma unroll
            for (int j = 0; j < 8; j++) arow[j] = make_float4(0.f, 0.f, 0.f, 0.f);
        }
    }
    if (tid < BM) sB[tid] = (m0 + tid < NN) ? __ldg(&batch[m0 + tid]) : -1;
    __syncthreads();

    int ty = tid >> 4, tx = tid & 15;
    float acc[4][8];
#pragma unroll
    for (int i = 0; i < 4; i++)
#pragma unroll
        for (int j = 0; j < 8; j++) acc[i][j] = 0.f;
    const float* A0 = sA + (ty * 4) * SA2_STRIDE;
#pragma unroll 4
    for (int k = 0; k < DH; k++) {
        float areg[4];
#pragma unroll
        for (int i = 0; i < 4; i++) areg[i] = A0[i * SA2_STRIDE + k];
        float4 bv0 = *(const float4*)(sW + k * DH + tx * 8);
        float4 bv1 = *(const float4*)(sW + k * DH + tx * 8 + 4);
        float breg[8] = {bv0.x, bv0.y, bv0.z, bv0.w, bv1.x, bv1.y, bv1.z, bv1.w};
#pragma unroll
        for (int i = 0; i < 4; i++)
#pragma unroll
            for (int j = 0; j < 8; j++) acc[i][j] += areg[i] * breg[j];
    }

    float al[8], bt[8];
#pragma unroll
    for (int j = 0; j < 8; j++) {
        int c = tx * 8 + j;
        float aa = __ldg(&bng[l * DH + c]) * BN_SCALE;
        al[j] = aa;
        bt[j] = aa * __ldg(&b2[l * DH + c]) + __ldg(&bnb[l * DH + c]);
    }
    __syncthreads();   // everyone done reading sA; safe to overwrite with h tile
#pragma unroll
    for (int i = 0; i < 4; i++) {
        int nodei = m0 + ty * 4 + i;
        if (nodei < NN) {
            float v[8];
#pragma unroll
            for (int j = 0; j < 8; j++) v[j] = fmaxf(al[j] * acc[i][j] + bt[j], 0.f);
            float4* dst = (float4*)(hout + (size_t)nodei * DH + tx * 8);
            dst[0] = make_float4(v[0], v[1], v[2], v[3]);
            dst[1] = make_float4(v[4], v[5], v[6], v[7]);
            float* hr = sA + (ty * 4 + i) * SA2_STRIDE + tx * 8;
            ((float4*)hr)[0] = make_float4(v[0], v[1], v[2], v[3]);
            ((float4*)hr)[1] = make_float4(v[4], v[5], v[6], v[7]);
        }
    }
    __syncthreads();

    // per-graph pooling: 2 thread-halves x 128 cols, 32 rows each
    int c = tid & 127, part = tid >> 7;
    int r0 = part * 32;
    float s = 0.f;
    int curg = -1;
    for (int rr = r0; rr < r0 + 32; rr++) {
        int noder = m0 + rr;
        if (noder >= NN) break;
        int g = sB[rr];
        if (g != curg) {
            if (curg >= 0) atomicAdd(&pool[curg * DH + c], s);
            s = 0.f; curg = g;
        }
        s += sA[rr * SA2_STRIDE + c];
    }
    if (curg >= 0) atomicAdd(&pool[curg * DH + c], s);
}

// ---------------------------------------------------------------------------
__global__ void k_final(const float* __restrict__ pool,
                        const float* __restrict__ Wp,
                        const float* __restrict__ bp,
                        float* __restrict__ out) {
    int t = threadIdx.x;
    if (t >= NG * DOUT) return;
    int g = t / DOUT, o = t % DOUT;
    float s = 0.f;
#pragma unroll
    for (int l = 0; l < NL + 1; l++) s += __ldg(&bp[l * DOUT + o]);
#pragma unroll
    for (int l = 0; l < NL + 1; l++) {
        const float* P = pool + l * NG * DH + g * DH;
        const float* W = Wp + l * DH * DOUT;
        for (int k = 0; k < DH; k++) s += P[k] * __ldg(&W[k * DOUT + o]);
    }
    out[t] = s;
}

// ---------------------------------------------------------------------------
extern "C" void kernel_launch(void* const* d_in, const int* in_sizes, int n_in,
                              void* d_out, int out_size) {
    const float* x    = (const float*)d_in[0];
    const float* eatt = (const float*)d_in[1];
    const float* eps  = (const float*)d_in[2];
    const float* W1   = (const float*)d_in[3];
    const float* b1   = (const float*)d_in[4];
    const float* g1   = (const float*)d_in[5];
    const float* be1  = (const float*)d_in[6];
    const float* W2   = (const float*)d_in[7];
    const float* b2   = (const float*)d_in[8];
    const float* bng  = (const float*)d_in[9];
    const float* bnb  = (const float*)d_in[10];
    const float* Wp   = (const float*)d_in[11];
    const float* bp   = (const float*)d_in[12];
    const int* edge_dst = (const int*)d_in[14];
    const int* batch    = (const int*)d_in[15];
    float* out = (float*)d_out;

    float *p_h1, *p_hb0, *p_hb1, *p_er, *p_pool;
    cudaGetSymbolAddress((void**)&p_h1,  g_h1);
    cudaGetSymbolAddress((void**)&p_hb0, g_hb0);
    cudaGetSymbolAddress((void**)&p_hb1, g_hb1);
    cudaGetSymbolAddress((void**)&p_er,  g_edge_rep);
    cudaGetSymbolAddress((void**)&p_pool, g_pool);

    const int SMEM_GG1 = (DC * DH + BM * SA1_STRIDE) * 4;                 // 111616
    const int SMEM_G2  = (DH * DH + BM * SA2_STRIDE) * 4 + BM * 4;        //  99584
    cudaFuncSetAttribute(k_gg1,   cudaFuncAttributeMaxDynamicSharedMemorySize, SMEM_GG1);
    cudaFuncSetAttribute(k_gemm2, cudaFuncAttributeMaxDynamicSharedMemorySize, SMEM_G2);

    k_zero<<<(POOLN + 255) / 256, 256>>>(p_pool, POOLN);
    k_edge_rep<<<(NN * FE + 255) / 256, 256>>>(eatt, p_er);
    k_pool_rep<<<(NN + 255) / 256, 128>>>(x, batch, p_pool);   // rep 0 = x

    const float* hin = x;
    float* bufs[2] = {p_hb0, p_hb1};
    for (int l = 0; l < NL; l++) {
        k_gg1<<<GRID_M, 256, SMEM_GG1>>>(hin, edge_dst, eps, l, W1, b1, g1, be1, p_er, p_h1);
        float* hout = bufs[l & 1];
        k_gemm2<<<GRID_M, 256, SMEM_G2>>>(p_h1, l, W2, b2, bng, bnb, batch, hout,
                                          p_pool + (size_t)(l + 1) * NG * DH);
        hin = hout;
    }
    k_final<<<1, NG * DOUT>>>(p_pool, Wp, bp, out);
}

// round 4
// speedup vs baseline: 1.3873x; 1.3873x over previous
#include <cuda_runtime.h>
#include <cstdint>
#include <cstddef>

#define NN   50000
#define DEG  16
#define FE   16
#define DH   128
#define DC   144
#define NL   3
#define NG   64
#define DOUT 10
#define BN_SCALE 0.9999950000374997f

#define BM   128
#define GRID_L ((NN + BM - 1) / BM)     // 391
#define POOLN ((NL + 1) * NG * DH)      // 32768

// strides in floats
#define AS 148     // A tile stride (K=144 + pad)
#define WS 132     // W / h1 / ht stride (128 + pad)

// float-index smem offsets
#define F_AL1 0
#define F_BE1 128
#define F_AL2 256
#define F_BE2 384
#define F_BT  512                       // int batch tile
#define F_W1  640
#define F_W2  (F_W1 + DC * WS)          // 19648
#define F_A   (F_W2 + DH * WS)          // 36544
#define SMEM_FLOATS (F_A + BM * AS)     // 55488
#define SMEM_BYTES  (SMEM_FLOATS * 4)   // 221952
#define F_H1 F_W1                       // h1 tile overlays W1 after GEMM1
#define F_HT F_A                        // h-out tile overlays A after GEMM2

// ---- device scratch ----
__device__ float g_hb0[(size_t)NN * DH];
__device__ float g_hb1[(size_t)NN * DH];
__device__ float g_edge_rep[(size_t)NN * FE];
__device__ float g_pool[POOLN];

// ---------------- helpers ----------------
__device__ __forceinline__ uint32_t tf32r(float x) {
    uint32_t r; asm("cvt.rna.tf32.f32 %0, %1;" : "=r"(r) : "f"(x)); return r;
}
__device__ __forceinline__ void mma_tf32(float* d,
                                         uint32_t a0, uint32_t a1, uint32_t a2, uint32_t a3,
                                         uint32_t b0, uint32_t b1) {
    asm volatile(
        "mma.sync.aligned.m16n8k8.row.col.f32.tf32.tf32.f32 "
        "{%0,%1,%2,%3}, {%4,%5,%6,%7}, {%8,%9}, {%0,%1,%2,%3};"
        : "+f"(d[0]), "+f"(d[1]), "+f"(d[2]), "+f"(d[3])
        : "r"(a0), "r"(a1), "r"(a2), "r"(a3), "r"(b0), "r"(b1));
}

// ---------------- small kernels ----------------
__global__ void k_zero(float* __restrict__ p, int n) {
    int i = blockIdx.x * blockDim.x + threadIdx.x;
    if (i < n) p[i] = 0.f;
}
__global__ void k_edge_rep(const float* __restrict__ ea, float* __restrict__ er) {
    int t = blockIdx.x * blockDim.x + threadIdx.x;
    if (t >= NN * FE) return;
    int i = t >> 4, f = t & 15;
    const float* base = ea + ((size_t)i * DEG) * FE + f;
    float s = 1.f;
#pragma unroll
    for (int k = 0; k < DEG; k++) s += __ldg(base + k * FE);
    er[t] = s;
}
__global__ void k_pool_rep(const float* __restrict__ h, const int* __restrict__ batch,
                           float* __restrict__ pool) {
    int c = threadIdx.x, m0 = blockIdx.x * 256;
    float s = 0.f; int curg = -1;
    for (int r = 0; r < 256; r++) {
        int node = m0 + r;
        if (node >= NN) break;
        int g = __ldg(&batch[node]);
        if (g != curg) { if (curg >= 0) atomicAdd(&pool[curg * DH + c], s); s = 0.f; curg = g; }
        s += __ldg(&h[(size_t)node * DH + c]);
    }
    if (curg >= 0) atomicAdd(&pool[curg * DH + c], s);
}
__global__ void k_final(const float* __restrict__ pool, const float* __restrict__ Wp,
                        const float* __restrict__ bp, float* __restrict__ out) {
    int t = threadIdx.x;
    if (t >= NG * DOUT) return;
    int g = t / DOUT, o = t % DOUT;
    float s = 0.f;
#pragma unroll
    for (int l = 0; l < NL + 1; l++) s += __ldg(&bp[l * DOUT + o]);
#pragma unroll
    for (int l = 0; l < NL + 1; l++) {
        const float* P = pool + l * NG * DH + g * DH;
        const float* W = Wp + l * DH * DOUT;
        for (int k = 0; k < DH; k++) s += P[k] * __ldg(&W[k * DOUT + o]);
    }
    out[t] = s;
}

// ---------------------------------------------------------------------------
// One full GIN layer: gather + GEMM1 + BN + ReLU + GEMM2 + BN + ReLU + pool.
__global__ void __launch_bounds__(256, 1)
k_layer(const float* __restrict__ hin, const int* __restrict__ edge_dst,
        const float* __restrict__ eps, int l,
        const float* __restrict__ W1, const float* __restrict__ b1,
        const float* __restrict__ g1, const float* __restrict__ be1,
        const float* __restrict__ er,
        const float* __restrict__ W2, const float* __restrict__ b2,
        const float* __restrict__ bng, const float* __restrict__ bnb,
        const int* __restrict__ batch,
        float* __restrict__ hout, float* __restrict__ pool) {
    extern __shared__ float sm[];
    uint32_t* smu = (uint32_t*)sm;
    int tid = threadIdx.x, wid = tid >> 5, lane = tid & 31;
    int m0 = blockIdx.x * BM;
    int g = lane >> 2, t = lane & 3;
    int wm = wid & 1, wn = wid >> 1;      // warp grid: 2 (M) x 4 (N)

    // BN constants + batch tile
    if (tid < DH) {
        float a1v = __ldg(&g1[l * DH + tid]) * BN_SCALE;
        sm[F_AL1 + tid] = a1v;
        sm[F_BE1 + tid] = a1v * __ldg(&b1[l * DH + tid]) + __ldg(&be1[l * DH + tid]);
        float a2v = __ldg(&bng[l * DH + tid]) * BN_SCALE;
        sm[F_AL2 + tid] = a2v;
        sm[F_BE2 + tid] = a2v * __ldg(&b2[l * DH + tid]) + __ldg(&bnb[l * DH + tid]);
        ((int*)sm)[F_BT + tid] = (m0 + tid < NN) ? __ldg(&batch[m0 + tid]) : -1;
    }
    // weights (tf32 bits), [k][n] with stride WS
    {
        const float* W1l = W1 + (size_t)l * DC * DH;
        for (int idx = tid; idx < DC * DH; idx += 256) {
            int k = idx >> 7, n = idx & 127;
            smu[F_W1 + k * WS + n] = tf32r(__ldg(&W1l[idx]));
        }
        const float* W2l = W2 + (size_t)l * DH * DH;
        for (int idx = tid; idx < DH * DH; idx += 256) {
            int k = idx >> 7, n = idx & 127;
            smu[F_W2 + k * WS + n] = tf32r(__ldg(&W2l[idx]));
        }
    }
    // gather -> A tile (tf32 bits), row-major stride AS
    float epsv = __ldg(&eps[l]);
    {
        int r = tid >> 1, half = tid & 1;
        int node = m0 + r;
        uint32_t* arow = smu + F_A + r * AS + half * 64;
        if (node < NN) {
            float4 a[16];
            const float4* hr = (const float4*)(hin + (size_t)node * DH) + half * 16;
            float e1 = 1.f + epsv;
#pragma unroll
            for (int j = 0; j < 16; j++) {
                float4 v = __ldg(hr + j);
                a[j].x = v.x * e1; a[j].y = v.y * e1; a[j].z = v.z * e1; a[j].w = v.w * e1;
            }
            const int4* ed4 = (const int4*)(edge_dst + (size_t)node * DEG);
            int4 e0 = __ldg(ed4), e1i = __ldg(ed4 + 1), e2 = __ldg(ed4 + 2), e3 = __ldg(ed4 + 3);
            int ds[16] = {e0.x, e0.y, e0.z, e0.w, e1i.x, e1i.y, e1i.z, e1i.w,
                          e2.x, e2.y, e2.z, e2.w, e3.x, e3.y, e3.z, e3.w};
#pragma unroll
            for (int k = 0; k < 16; k++) {
                const float4* nr = (const float4*)(hin + (size_t)ds[k] * DH) + half * 16;
#pragma unroll
                for (int j = 0; j < 16; j++) {
                    float4 v = __ldg(nr + j);
                    a[j].x += v.x; a[j].y += v.y; a[j].z += v.z; a[j].w += v.w;
                }
            }
#pragma unroll
            for (int j = 0; j < 16; j++)
                *(uint4*)(arow + j * 4) =
                    make_uint4(tf32r(a[j].x), tf32r(a[j].y), tf32r(a[j].z), tf32r(a[j].w));
            if (half) {  // edge-feature columns 128..143
                const float4* ep = (const float4*)(er + (size_t)node * FE);
                uint32_t* erow = smu + F_A + r * AS + 128;
#pragma unroll
                for (int q = 0; q < 4; q++) {
                    float4 v = __ldg(ep + q);
                    *(uint4*)(erow + q * 4) =
                        make_uint4(tf32r(v.x + epsv), tf32r(v.y + epsv),
                                   tf32r(v.z + epsv), tf32r(v.w + epsv));
                }
            }
        } else {
            uint4 z = make_uint4(0, 0, 0, 0);
#pragma unroll
            for (int j = 0; j < 16; j++) *(uint4*)(arow + j * 4) = z;
            if (half) {
                uint32_t* erow = smu + F_A + r * AS + 128;
#pragma unroll
                for (int q = 0; q < 4; q++) *(uint4*)(erow + q * 4) = z;
            }
        }
    }
    __syncthreads();

    float acc[4][4][4];
    // ---- GEMM1: [128x144] x [144x128] ----
#pragma unroll
    for (int mi = 0; mi < 4; mi++)
#pragma unroll
        for (int nj = 0; nj < 4; nj++)
#pragma unroll
            for (int q = 0; q < 4; q++) acc[mi][nj][q] = 0.f;
    {
        const uint32_t* Ab = smu + F_A;
        const uint32_t* Bb = smu + F_W1;
#pragma unroll 2
        for (int ks = 0; ks < 18; ks++) {
            int k0 = ks * 8;
            uint32_t af[4][4], bf[4][2];
#pragma unroll
            for (int mi = 0; mi < 4; mi++) {
                int r = wm * 64 + mi * 16;
                af[mi][0] = Ab[(r + g) * AS + k0 + t];
                af[mi][1] = Ab[(r + g + 8) * AS + k0 + t];
                af[mi][2] = Ab[(r + g) * AS + k0 + 4 + t];
                af[mi][3] = Ab[(r + g + 8) * AS + k0 + 4 + t];
            }
#pragma unroll
            for (int nj = 0; nj < 4; nj++) {
                int c = wn * 32 + nj * 8;
                bf[nj][0] = Bb[(k0 + t) * WS + c + g];
                bf[nj][1] = Bb[(k0 + 4 + t) * WS + c + g];
            }
#pragma unroll
            for (int mi = 0; mi < 4; mi++)
#pragma unroll
                for (int nj = 0; nj < 4; nj++)
                    mma_tf32(acc[mi][nj], af[mi][0], af[mi][1], af[mi][2], af[mi][3],
                             bf[nj][0], bf[nj][1]);
        }
    }
    __syncthreads();   // all warps done reading W1 + A region

    // ---- epilogue1: BN + ReLU -> sH1 (tf32 bits) ----
#pragma unroll
    for (int mi = 0; mi < 4; mi++)
#pragma unroll
        for (int nj = 0; nj < 4; nj++) {
            int col = wn * 32 + nj * 8 + 2 * t;
            float al0 = sm[F_AL1 + col], al1v = sm[F_AL1 + col + 1];
            float be0 = sm[F_BE1 + col], be1v = sm[F_BE1 + col + 1];
#pragma unroll
            for (int pp = 0; pp < 2; pp++) {
                int row = wm * 64 + mi * 16 + g + pp * 8;
                float v0 = fmaxf(al0 * acc[mi][nj][pp * 2] + be0, 0.f);
                float v1 = fmaxf(al1v * acc[mi][nj][pp * 2 + 1] + be1v, 0.f);
                *(uint2*)(smu + F_H1 + row * WS + col) = make_uint2(tf32r(v0), tf32r(v1));
            }
        }
    __syncthreads();

    // ---- GEMM2: [128x128] x [128x128] ----
#pragma unroll
    for (int mi = 0; mi < 4; mi++)
#pragma unroll
        for (int nj = 0; nj < 4; nj++)
#pragma unroll
            for (int q = 0; q < 4; q++) acc[mi][nj][q] = 0.f;
    {
        const uint32_t* Ab = smu + F_H1;
        const uint32_t* Bb = smu + F_W2;
#pragma unroll 2
        for (int ks = 0; ks < 16; ks++) {
            int k0 = ks * 8;
            uint32_t af[4][4], bf[4][2];
#pragma unroll
            for (int mi = 0; mi < 4; mi++) {
                int r = wm * 64 + mi * 16;
                af[mi][0] = Ab[(r + g) * WS + k0 + t];
                af[mi][1] = Ab[(r + g + 8) * WS + k0 + t];
                af[mi][2] = Ab[(r + g) * WS + k0 + 4 + t];
                af[mi][3] = Ab[(r + g + 8) * WS + k0 + 4 + t];
            }
#pragma unroll
            for (int nj = 0; nj < 4; nj++) {
                int c = wn * 32 + nj * 8;
                bf[nj][0] = Bb[(k0 + t) * WS + c + g];
                bf[nj][1] = Bb[(k0 + 4 + t) * WS + c + g];
            }
#pragma unroll
            for (int mi = 0; mi < 4; mi++)
#pragma unroll
                for (int nj = 0; nj < 4; nj++)
                    mma_tf32(acc[mi][nj], af[mi][0], af[mi][1], af[mi][2], af[mi][3],
                             bf[nj][0], bf[nj][1]);
        }
    }

    // ---- epilogue2: BN + ReLU -> sHt (floats; overlays A region) ----
#pragma unroll
    for (int mi = 0; mi < 4; mi++)
#pragma unroll
        for (int nj = 0; nj < 4; nj++) {
            int col = wn * 32 + nj * 8 + 2 * t;
            float al0 = sm[F_AL2 + col], al1v = sm[F_AL2 + col + 1];
            float be0 = sm[F_BE2 + col], be1v = sm[F_BE2 + col + 1];
#pragma unroll
            for (int pp = 0; pp < 2; pp++) {
                int row = wm * 64 + mi * 16 + g + pp * 8;
                float v0 = fmaxf(al0 * acc[mi][nj][pp * 2] + be0, 0.f);
                float v1 = fmaxf(al1v * acc[mi][nj][pp * 2 + 1] + be1v, 0.f);
                *(float2*)(sm + F_HT + row * WS + col) = make_float2(v0, v1);
            }
        }
    __syncthreads();

    // ---- write hout (coalesced) ----
    for (int idx = tid; idx < BM * 32; idx += 256) {
        int r = idx >> 5, q = idx & 31;
        if (m0 + r < NN)
            ((float4*)(hout + (size_t)(m0 + r) * DH))[q] = *(float4*)(sm + F_HT + r * WS + q * 4);
    }
    // ---- per-graph pooling ----
    {
        int c = tid & 127, part = tid >> 7;
        int r0 = part * 64;
        float s = 0.f; int curg = -1;
        const int* sBt = (const int*)sm + F_BT;
        for (int rr = r0; rr < r0 + 64; rr++) {
            if (m0 + rr >= NN) break;
            int gg = sBt[rr];
            if (gg != curg) { if (curg >= 0) atomicAdd(&pool[curg * DH + c], s); s = 0.f; curg = gg; }
            s += sm[F_HT + rr * WS + c];
        }
        if (curg >= 0) atomicAdd(&pool[curg * DH + c], s);
    }
}

// ---------------------------------------------------------------------------
extern "C" void kernel_launch(void* const* d_in, const int* in_sizes, int n_in,
                              void* d_out, int out_size) {
    const float* x    = (const float*)d_in[0];
    const float* eatt = (const float*)d_in[1];
    const float* eps  = (const float*)d_in[2];
    const float* W1   = (const float*)d_in[3];
    const float* b1   = (const float*)d_in[4];
    const float* g1   = (const float*)d_in[5];
    const float* be1  = (const float*)d_in[6];
    const float* W2   = (const float*)d_in[7];
    const float* b2   = (const float*)d_in[8];
    const float* bng  = (const float*)d_in[9];
    const float* bnb  = (const float*)d_in[10];
    const float* Wp   = (const float*)d_in[11];
    const float* bp   = (const float*)d_in[12];
    const int* edge_dst = (const int*)d_in[14];
    const int* batch    = (const int*)d_in[15];
    float* out = (float*)d_out;

    float *p_hb0, *p_hb1, *p_er, *p_pool;
    cudaGetSymbolAddress((void**)&p_hb0, g_hb0);
    cudaGetSymbolAddress((void**)&p_hb1, g_hb1);
    cudaGetSymbolAddress((void**)&p_er,  g_edge_rep);
    cudaGetSymbolAddress((void**)&p_pool, g_pool);

    cudaFuncSetAttribute(k_layer, cudaFuncAttributeMaxDynamicSharedMemorySize, SMEM_BYTES);

    k_zero<<<(POOLN + 255) / 256, 256>>>(p_pool, POOLN);
    k_edge_rep<<<(NN * FE + 255) / 256, 256>>>(eatt, p_er);
    k_pool_rep<<<(NN + 255) / 256, 128>>>(x, batch, p_pool);

    const float* hin = x;
    float* bufs[2] = {p_hb0, p_hb1};
    for (int l = 0; l < NL; l++) {
        float* hout = bufs[l & 1];
        k_layer<<<GRID_L, 256, SMEM_BYTES>>>(hin, edge_dst, eps, l,
                                             W1, b1, g1, be1, p_er,
                                             W2, b2, bng, bnb, batch,
                                             hout, p_pool + (size_t)(l + 1) * NG * DH);
        hin = hout;
    }
    k_final<<<1, NG * DOUT>>>(p_pool, Wp, bp, out);
}

// round 5
// speedup vs baseline: 1.6526x; 1.1912x over previous
#include <cuda_runtime.h>
#include <cstdint>
#include <cstddef>

#define NN   50000
#define DEG  16
#define FE   16
#define DH   128
#define DC   144
#define NL   3
#define NG   64
#define DOUT 10
#define BN_SCALE 0.9999950000374997f

#define BM   128
#define GRID_L ((NN + BM - 1) / BM)     // 391
#define POOLN ((NL + 1) * NG * DH)      // 32768

#define AS   148    // A / h1 stride (floats): bank-safe for af (20g+t)
#define WS1  136    // W stride: bank-safe for bf (8t+g)
#define HTS  132    // ht stride (pooling)

// float-index smem offsets (k_mma)
#define F_AL1 0
#define F_BE1 128
#define F_AL2 256
#define F_BE2 384
#define F_BT  512
#define F_W1  640
#define F_W2  (F_W1 + DC * WS1)          // 20224
#define F_A   (F_W2 + DH * WS1)          // 37632
#define SMEM_FLOATS (F_A + BM * AS)      // 56576
#define SMEM_BYTES  (SMEM_FLOATS * 4)    // 226304
#define F_H1  F_A                        // h1 overlays A (stride AS)
#define F_HT  F_W1                       // ht overlays W1 (stride HTS)

// ---- device scratch ----
__device__ uint32_t g_A[(size_t)NN * AS];          // tf32 pooled features
__device__ float g_hb0[(size_t)NN * DH];
__device__ float g_hb1[(size_t)NN * DH];
__device__ float g_edge_rep[(size_t)NN * FE];
__device__ float g_pool[POOLN];

// ---------------- helpers ----------------
__device__ __forceinline__ uint32_t tf32r(float x) {
    uint32_t r; asm("cvt.rna.tf32.f32 %0, %1;" : "=r"(r) : "f"(x)); return r;
}
__device__ __forceinline__ void mma_tf32(float* d,
                                         uint32_t a0, uint32_t a1, uint32_t a2, uint32_t a3,
                                         uint32_t b0, uint32_t b1) {
    asm volatile(
        "mma.sync.aligned.m16n8k8.row.col.f32.tf32.tf32.f32 "
        "{%0,%1,%2,%3}, {%4,%5,%6,%7}, {%8,%9}, {%0,%1,%2,%3};"
        : "+f"(d[0]), "+f"(d[1]), "+f"(d[2]), "+f"(d[3])
        : "r"(a0), "r"(a1), "r"(a2), "r"(a3), "r"(b0), "r"(b1));
}

// ---------------- small kernels ----------------
__global__ void k_zero(float* __restrict__ p, int n) {
    int i = blockIdx.x * blockDim.x + threadIdx.x;
    if (i < n) p[i] = 0.f;
}
__global__ void k_edge_rep(const float* __restrict__ ea, float* __restrict__ er) {
    int t = blockIdx.x * blockDim.x + threadIdx.x;
    if (t >= NN * FE) return;
    int i = t >> 4, f = t & 15;
    const float* base = ea + ((size_t)i * DEG) * FE + f;
    float s = 1.f;
#pragma unroll
    for (int k = 0; k < DEG; k++) s += __ldg(base + k * FE);
    er[t] = s;
}
__global__ void k_pool_rep(const float* __restrict__ h, const int* __restrict__ batch,
                           float* __restrict__ pool) {
    int c = threadIdx.x, m0 = blockIdx.x * 256;
    float s = 0.f; int curg = -1;
    for (int r = 0; r < 256; r++) {
        int node = m0 + r;
        if (node >= NN) break;
        int g = __ldg(&batch[node]);
        if (g != curg) { if (curg >= 0) atomicAdd(&pool[curg * DH + c], s); s = 0.f; curg = g; }
        s += __ldg(&h[(size_t)node * DH + c]);
    }
    if (curg >= 0) atomicAdd(&pool[curg * DH + c], s);
}
__global__ void k_final(const float* __restrict__ pool, const float* __restrict__ Wp,
                        const float* __restrict__ bp, float* __restrict__ out) {
    int t = threadIdx.x;
    if (t >= NG * DOUT) return;
    int g = t / DOUT, o = t % DOUT;
    float s = 0.f;
#pragma unroll
    for (int l = 0; l < NL + 1; l++) s += __ldg(&bp[l * DOUT + o]);
#pragma unroll
    for (int l = 0; l < NL + 1; l++) {
        const float* P = pool + l * NG * DH + g * DH;
        const float* W = Wp + l * DH * DOUT;
        for (int k = 0; k < DH; k++) s += P[k] * __ldg(&W[k * DOUT + o]);
    }
    out[t] = s;
}

// ---------------------------------------------------------------------------
// Gather: A[node] = [(1+eps)*h[node] + sum_k h[dst], er[node]+eps]  (tf32 bits)
// 4 threads per node, 32 cols each. No smem -> high occupancy, max MLP.
__global__ void __launch_bounds__(256) k_gather(
    const float* __restrict__ hin, const int* __restrict__ edge_dst,
    const float* __restrict__ eps, int l,
    const float* __restrict__ er, uint32_t* __restrict__ A) {
    int t4 = blockIdx.x * 256 + threadIdx.x;
    if (t4 >= NN * 4) return;
    int node = t4 >> 2, q = t4 & 3;
    float epsv = __ldg(&eps[l]);
    float e1 = 1.f + epsv;

    float4 a[8];
    const float4* hr = (const float4*)(hin + (size_t)node * DH) + q * 8;
#pragma unroll
    for (int j = 0; j < 8; j++) {
        float4 v = __ldg(hr + j);
        a[j].x = v.x * e1; a[j].y = v.y * e1; a[j].z = v.z * e1; a[j].w = v.w * e1;
    }
    const int4* ed4 = (const int4*)(edge_dst + (size_t)node * DEG);
    int4 e0 = __ldg(ed4), e1i = __ldg(ed4 + 1), e2 = __ldg(ed4 + 2), e3 = __ldg(ed4 + 3);
    int ds[16] = {e0.x, e0.y, e0.z, e0.w, e1i.x, e1i.y, e1i.z, e1i.w,
                  e2.x, e2.y, e2.z, e2.w, e3.x, e3.y, e3.z, e3.w};
#pragma unroll
    for (int k = 0; k < DEG; k++) {
        const float4* nr = (const float4*)(hin + (size_t)ds[k] * DH) + q * 8;
#pragma unroll
        for (int j = 0; j < 8; j++) {
            float4 v = __ldg(nr + j);
            a[j].x += v.x; a[j].y += v.y; a[j].z += v.z; a[j].w += v.w;
        }
    }
    uint32_t* arow = A + (size_t)node * AS + q * 32;
#pragma unroll
    for (int j = 0; j < 8; j++)
        *(uint4*)(arow + j * 4) = make_uint4(tf32r(a[j].x), tf32r(a[j].y),
                                             tf32r(a[j].z), tf32r(a[j].w));
    float4 v = __ldg((const float4*)(er + (size_t)node * FE) + q);
    *(uint4*)(A + (size_t)node * AS + 128 + q * 4) =
        make_uint4(tf32r(v.x + epsv), tf32r(v.y + epsv), tf32r(v.z + epsv), tf32r(v.w + epsv));
}

// ---------------------------------------------------------------------------
// MMA: GEMM1 + BN/ReLU + GEMM2 + BN/ReLU + per-graph pool. 512 threads.
__global__ void __launch_bounds__(512, 1) k_mma(
    const uint32_t* __restrict__ A, int l,
    const float* __restrict__ W1, const float* __restrict__ b1,
    const float* __restrict__ g1, const float* __restrict__ be1,
    const float* __restrict__ W2, const float* __restrict__ b2,
    const float* __restrict__ bng, const float* __restrict__ bnb,
    const int* __restrict__ batch,
    float* __restrict__ hout, float* __restrict__ pool) {
    extern __shared__ float sm[];
    uint32_t* smu = (uint32_t*)sm;
    int tid = threadIdx.x, wid = tid >> 5, lane = tid & 31;
    int m0 = blockIdx.x * BM;
    int g = lane >> 2, t = lane & 3;
    int wm = wid & 3, wn = wid >> 2;     // 4 (M) x 4 (N) warps, tile 32x32

    if (tid < DH) {
        float a1v = __ldg(&g1[l * DH + tid]) * BN_SCALE;
        sm[F_AL1 + tid] = a1v;
        sm[F_BE1 + tid] = a1v * __ldg(&b1[l * DH + tid]) + __ldg(&be1[l * DH + tid]);
        float a2v = __ldg(&bng[l * DH + tid]) * BN_SCALE;
        sm[F_AL2 + tid] = a2v;
        sm[F_BE2 + tid] = a2v * __ldg(&b2[l * DH + tid]) + __ldg(&bnb[l * DH + tid]);
        ((int*)sm)[F_BT + tid] = (m0 + tid < NN) ? __ldg(&batch[m0 + tid]) : -1;
    }
    {   // weights -> smem (tf32 bits), stride WS1
        const float* W1l = W1 + (size_t)l * DC * DH;
        for (int idx = tid; idx < DC * DH; idx += 512) {
            int k = idx >> 7, n = idx & 127;
            smu[F_W1 + k * WS1 + n] = tf32r(__ldg(&W1l[idx]));
        }
        const float* W2l = W2 + (size_t)l * DH * DH;
        for (int idx = tid; idx < DH * DH; idx += 512) {
            int k = idx >> 7, n = idx & 127;
            smu[F_W2 + k * WS1 + n] = tf32r(__ldg(&W2l[idx]));
        }
    }
    {   // A tile: straight coalesced copy (g_A stride == smem stride == AS)
        int nrow = NN - m0; if (nrow > BM) nrow = BM;
        int nf4 = nrow * (AS / 4);
        const uint4* gsrc = (const uint4*)(A + (size_t)m0 * AS);
        uint4* sdst = (uint4*)(smu + F_A);
        for (int idx = tid; idx < BM * (AS / 4); idx += 512)
            sdst[idx] = (idx < nf4) ? __ldg(gsrc + idx) : make_uint4(0, 0, 0, 0);
    }
    __syncthreads();

    float acc[2][4][4];
    // ---- GEMM1: [128x144] @ [144x128] ----
#pragma unroll
    for (int mi = 0; mi < 2; mi++)
#pragma unroll
        for (int nj = 0; nj < 4; nj++)
#pragma unroll
            for (int q = 0; q < 4; q++) acc[mi][nj][q] = 0.f;
    {
        const uint32_t* Ab = smu + F_A;
        const uint32_t* Bb = smu + F_W1;
#pragma unroll 3
        for (int ks = 0; ks < 18; ks++) {
            int k0 = ks * 8;
            uint32_t af[2][4], bf[4][2];
#pragma unroll
            for (int mi = 0; mi < 2; mi++) {
                int r = wm * 32 + mi * 16;
                af[mi][0] = Ab[(r + g) * AS + k0 + t];
                af[mi][1] = Ab[(r + g + 8) * AS + k0 + t];
                af[mi][2] = Ab[(r + g) * AS + k0 + 4 + t];
                af[mi][3] = Ab[(r + g + 8) * AS + k0 + 4 + t];
            }
#pragma unroll
            for (int nj = 0; nj < 4; nj++) {
                int c = wn * 32 + nj * 8;
                bf[nj][0] = Bb[(k0 + t) * WS1 + c + g];
                bf[nj][1] = Bb[(k0 + 4 + t) * WS1 + c + g];
            }
#pragma unroll
            for (int mi = 0; mi < 2; mi++)
#pragma unroll
                for (int nj = 0; nj < 4; nj++)
                    mma_tf32(acc[mi][nj], af[mi][0], af[mi][1], af[mi][2], af[mi][3],
                             bf[nj][0], bf[nj][1]);
        }
    }
    __syncthreads();

    // ---- epilogue1: BN + ReLU -> h1 (tf32 bits, overlays A) ----
#pragma unroll
    for (int mi = 0; mi < 2; mi++)
#pragma unroll
        for (int nj = 0; nj < 4; nj++) {
            int col = wn * 32 + nj * 8 + 2 * t;
            float al0 = sm[F_AL1 + col], al1v = sm[F_AL1 + col + 1];
            float be0 = sm[F_BE1 + col], be1v = sm[F_BE1 + col + 1];
#pragma unroll
            for (int pp = 0; pp < 2; pp++) {
                int row = wm * 32 + mi * 16 + g + pp * 8;
                float v0 = fmaxf(al0 * acc[mi][nj][pp * 2] + be0, 0.f);
                float v1 = fmaxf(al1v * acc[mi][nj][pp * 2 + 1] + be1v, 0.f);
                *(uint2*)(smu + F_H1 + row * AS + col) = make_uint2(tf32r(v0), tf32r(v1));
            }
        }
    __syncthreads();

    // ---- GEMM2: [128x128] @ [128x128] ----
#pragma unroll
    for (int mi = 0; mi < 2; mi++)
#pragma unroll
        for (int nj = 0; nj < 4; nj++)
#pragma unroll
            for (int q = 0; q < 4; q++) acc[mi][nj][q] = 0.f;
    {
        const uint32_t* Ab = smu + F_H1;
        const uint32_t* Bb = smu + F_W2;
#pragma unroll 4
        for (int ks = 0; ks < 16; ks++) {
            int k0 = ks * 8;
            uint32_t af[2][4], bf[4][2];
#pragma unroll
            for (int mi = 0; mi < 2; mi++) {
                int r = wm * 32 + mi * 16;
                af[mi][0] = Ab[(r + g) * AS + k0 + t];
                af[mi][1] = Ab[(r + g + 8) * AS + k0 + t];
                af[mi][2] = Ab[(r + g) * AS + k0 + 4 + t];
                af[mi][3] = Ab[(r + g + 8) * AS + k0 + 4 + t];
            }
#pragma unroll
            for (int nj = 0; nj < 4; nj++) {
                int c = wn * 32 + nj * 8;
                bf[nj][0] = Bb[(k0 + t) * WS1 + c + g];
                bf[nj][1] = Bb[(k0 + 4 + t) * WS1 + c + g];
            }
#pragma unroll
            for (int mi = 0; mi < 2; mi++)
#pragma unroll
                for (int nj = 0; nj < 4; nj++)
                    mma_tf32(acc[mi][nj], af[mi][0], af[mi][1], af[mi][2], af[mi][3],
                             bf[nj][0], bf[nj][1]);
        }
    }
    __syncthreads();   // all warps done reading W1-region? (W1 unused now) & h1

    // ---- epilogue2: BN + ReLU -> ht (floats, overlays W1 region) ----
#pragma unroll
    for (int mi = 0; mi < 2; mi++)
#pragma unroll
        for (int nj = 0; nj < 4; nj++) {
            int col = wn * 32 + nj * 8 + 2 * t;
            float al0 = sm[F_AL2 + col], al1v = sm[F_AL2 + col + 1];
            float be0 = sm[F_BE2 + col], be1v = sm[F_BE2 + col + 1];
#pragma unroll
            for (int pp = 0; pp < 2; pp++) {
                int row = wm * 32 + mi * 16 + g + pp * 8;
                float v0 = fmaxf(al0 * acc[mi][nj][pp * 2] + be0, 0.f);
                float v1 = fmaxf(al1v * acc[mi][nj][pp * 2 + 1] + be1v, 0.f);
                *(float2*)(sm + F_HT + row * HTS + col) = make_float2(v0, v1);
            }
        }
    __syncthreads();

    // ---- write hout (coalesced) ----
    for (int idx = tid; idx < BM * 32; idx += 512) {
        int r = idx >> 5, q = idx & 31;
        if (m0 + r < NN)
            ((float4*)(hout + (size_t)(m0 + r) * DH))[q] = *(float4*)(sm + F_HT + r * HTS + q * 4);
    }
    // ---- per-graph pooling: 4 parts x 128 cols, 32 rows each ----
    {
        int c = tid & 127, part = tid >> 7;
        int r0 = part * 32;
        float s = 0.f; int curg = -1;
        const int* sBt = (const int*)sm + F_BT;
        for (int rr = r0; rr < r0 + 32; rr++) {
            if (m0 + rr >= NN) break;
            int gg = sBt[rr];
            if (gg != curg) { if (curg >= 0) atomicAdd(&pool[curg * DH + c], s); s = 0.f; curg = gg; }
            s += sm[F_HT + rr * HTS + c];
        }
        if (curg >= 0) atomicAdd(&pool[curg * DH + c], s);
    }
}

// ---------------------------------------------------------------------------
extern "C" void kernel_launch(void* const* d_in, const int* in_sizes, int n_in,
                              void* d_out, int out_size) {
    const float* x    = (const float*)d_in[0];
    const float* eatt = (const float*)d_in[1];
    const float* eps  = (const float*)d_in[2];
    const float* W1   = (const float*)d_in[3];
    const float* b1   = (const float*)d_in[4];
    const float* g1   = (const float*)d_in[5];
    const float* be1  = (const float*)d_in[6];
    const float* W2   = (const float*)d_in[7];
    const float* b2   = (const float*)d_in[8];
    const float* bng  = (const float*)d_in[9];
    const float* bnb  = (const float*)d_in[10];
    const float* Wp   = (const float*)d_in[11];
    const float* bp   = (const float*)d_in[12];
    const int* edge_dst = (const int*)d_in[14];
    const int* batch    = (const int*)d_in[15];
    float* out = (float*)d_out;

    uint32_t* p_A; float *p_hb0, *p_hb1, *p_er, *p_pool;
    cudaGetSymbolAddress((void**)&p_A,   g_A);
    cudaGetSymbolAddress((void**)&p_hb0, g_hb0);
    cudaGetSymbolAddress((void**)&p_hb1, g_hb1);
    cudaGetSymbolAddress((void**)&p_er,  g_edge_rep);
    cudaGetSymbolAddress((void**)&p_pool, g_pool);

    cudaFuncSetAttribute(k_mma, cudaFuncAttributeMaxDynamicSharedMemorySize, SMEM_BYTES);

    k_zero<<<(POOLN + 255) / 256, 256>>>(p_pool, POOLN);
    k_edge_rep<<<(NN * FE + 255) / 256, 256>>>(eatt, p_er);
    k_pool_rep<<<(NN + 255) / 256, 128>>>(x, batch, p_pool);

    const float* hin = x;
    float* bufs[2] = {p_hb0, p_hb1};
    for (int l = 0; l < NL; l++) {
        float* hout = bufs[l & 1];
        k_gather<<<(NN * 4 + 255) / 256, 256>>>(hin, edge_dst, eps, l, p_er, p_A);
        k_mma<<<GRID_L, 512, SMEM_BYTES>>>(p_A, l, W1, b1, g1, be1,
                                           W2, b2, bng, bnb, batch,
                                           hout, p_pool + (size_t)(l + 1) * NG * DH);
        hin = hout;
    }
    k_final<<<1, NG * DOUT>>>(p_pool, Wp, bp, out);
}